// round 1
// baseline (speedup 1.0000x reference)
#include <cuda_runtime.h>
#include <cuda_bf16.h>
#include <cstdint>

#define BINS 20
#define NODES 21
#define NWARPS 8
#define THREADS 256
#define FRAC_SCALE 2097152.0f   /* 2^21 */
#define INV_FRAC_SCALE (1.0f/2097152.0f)
#define COUNT_SHIFT 44

// Scratch: packed (count, sum_frac) per (group, bin). Zeroed each launch.
__device__ unsigned long long g_hist[2 * BINS];

__global__ void hx_zero() {
    int i = threadIdx.x;
    if (i < 2 * BINS) g_hist[i] = 0ULL;
}

__device__ __forceinline__ void hx_accum(unsigned long long* my, float x, int g) {
    float t = x * (float)BINS;
    int k = (int)t;
    if (k > BINS - 1) k = BINS - 1;
    if (k < 0) k = 0;
    float frac = t - (float)k;
    frac = fminf(fmaxf(frac, 0.0f), 1.0f);
    unsigned long long pk = (1ULL << COUNT_SHIFT)
        | (unsigned long long)(frac * FRAC_SCALE + 0.5f);
    atomicAdd(&my[(g & 1) * BINS + k], pk);
}

__global__ __launch_bounds__(THREADS)
void hx_hist(const float* __restrict__ yp, const int* __restrict__ s, int n) {
    __shared__ unsigned long long sh[NWARPS][2 * BINS];
    const int tid = threadIdx.x;
    const int warp = tid >> 5;

    for (int i = tid; i < NWARPS * 2 * BINS; i += THREADS)
        (&sh[0][0])[i] = 0ULL;
    __syncthreads();

    unsigned long long* my = sh[warp];

    const int nvec = n >> 2;
    const float4* __restrict__ yp4 = (const float4*)yp;
    const int4*   __restrict__ s4p = (const int4*)s;
    const int stride = gridDim.x * THREADS;

    for (int i = blockIdx.x * THREADS + tid; i < nvec; i += stride) {
        float4 x4 = yp4[i];
        int4   g4 = s4p[i];
        hx_accum(my, x4.x, g4.x);
        hx_accum(my, x4.y, g4.y);
        hx_accum(my, x4.z, g4.z);
        hx_accum(my, x4.w, g4.w);
    }

    // tail (n not divisible by 4)
    {
        int rem_base = nvec << 2;
        int gtid = blockIdx.x * THREADS + tid;
        if (gtid < n - rem_base) {
            int idx = rem_base + gtid;
            hx_accum(my, yp[idx], s[idx]);
        }
    }

    __syncthreads();
    // block reduce across warp copies, one global atomic per slot
    for (int i = tid; i < 2 * BINS; i += THREADS) {
        unsigned long long acc = 0ULL;
        #pragma unroll
        for (int w = 0; w < NWARPS; w++) acc += sh[w][i];
        if (acc) atomicAdd(&g_hist[i], acc);
    }
}

__global__ void hx_final(float* __restrict__ out,
                         const float* __restrict__ p_a,
                         const float* __restrict__ p_b) {
    if (threadIdx.x != 0 || blockIdx.x != 0) return;

    float cnt[2][BINS], fr[2][BINS];
    for (int g = 0; g < 2; g++) {
        for (int b = 0; b < BINS; b++) {
            unsigned long long h = g_hist[g * BINS + b];
            cnt[g][b] = (float)(h >> COUNT_SHIFT);
            fr[g][b]  = (float)(h & ((1ULL << COUNT_SHIFT) - 1ULL)) * INV_FRAC_SCALE;
        }
    }

    float W[2][NODES];
    for (int g = 0; g < 2; g++) {
        for (int k = 0; k < NODES; k++) {
            float w = 0.0f;
            if (k < BINS) w += cnt[g][k] - fr[g][k];
            if (k > 0)    w += fr[g][k - 1];
            W[g][k] = w;
        }
    }

    float S0 = 0.0f, S1 = 0.0f;
    for (int k = 0; k < NODES; k++) { S0 += W[0][k]; S1 += W[1][k]; }
    float inv0 = (S0 > 0.0f) ? 1.0f / S0 : 0.0f;
    float inv1 = (S1 > 0.0f) ? 1.0f / S1 : 0.0f;

    // Python: int(BINS*pct) computed in double; snap f32 round-down (0.7f*20 =
    // 13.99999976) back up with a small epsilon before truncation.
    int a_bin = (int)floorf((float)BINS * p_a[0] + 1e-4f);
    int b_bin = (int)floorf((float)BINS * p_b[0] + 1e-4f);

    float loss = 0.0f;
    for (int k = 0; k < NODES; k++) {
        if (k >= a_bin && k < b_bin)
            loss += fabsf(W[0][k] * inv0 - W[1][k] * inv1);
    }
    out[0] = loss;
}

extern "C" void kernel_launch(void* const* d_in, const int* in_sizes, int n_in,
                              void* d_out, int out_size) {
    const float* y_pred = (const float*)d_in[0];
    const int*   s      = (const int*)d_in[1];
    // d_in[2] = y_gt (unused)
    const float* pct_a  = (const float*)d_in[3];
    const float* pct_b  = (const float*)d_in[4];
    float* out = (float*)d_out;
    int n = in_sizes[0];

    int nvec = n >> 2;
    int blocks = (nvec + THREADS - 1) / THREADS;
    if (blocks > 592) blocks = 592;   // 4 CTAs/SM-ish wave; grid-stride covers rest
    if (blocks < 1) blocks = 1;

    hx_zero<<<1, 64>>>();
    hx_hist<<<blocks, THREADS>>>(y_pred, s, n);
    hx_final<<<1, 32>>>(out, pct_a, pct_b);
}